// round 6
// baseline (speedup 1.0000x reference)
#include <cuda_runtime.h>

#define BB 64
#define NN 512
#define EPS 1e-10f

// Scratch (allocation-free rule: __device__ globals; zero-init at module load,
// reset by the finalize block each run for graph replay)
__device__ float4   g_items[BB * NN];   // rel-sorted: {gain, disc, exp(s), lo_as_int}
__device__ float    g_rowScale[BB];     // ln2 / (idcg * (cnt+eps)) / B
__device__ unsigned g_slot[BB * 5];     // within-bucket placement counters
__device__ unsigned g_rowDone[BB];      // prep-phase arrival counters
__device__ float    g_accum = 0.0f;
__device__ unsigned g_count = 0u;

// One fused kernel. grid (8, 64), 256 threads, all 512 blocks co-resident.
// Phase 1: block q of row computes ranks for items [q*64, q*64+64), places them
//          at relevance-sorted positions; q==0 also computes the row scale.
// Row barrier: per-row arrival counter (threadFenceReduction pattern).
// Phase 2: valid-pairs accumulation with warp-uniform bounds (broadcast LDS).
__global__ __launch_bounds__(256, 4)
void lr_fused(const float* __restrict__ scores,
              const float* __restrict__ relevance,
              float* __restrict__ out) {
    const int q   = blockIdx.x;      // 0..7 (prep chunk AND pairs chunk id)
    const int row = blockIdx.y;
    const int t   = threadIdx.x;

    __shared__ float4 sbuf[NN];      // phase1: float2 {score, rel}; phase2: items
    __shared__ int    counts[5];
    __shared__ float  wred[8];
    __shared__ float  ws[8];

    // ---------------- Phase 1: prep ----------------
    float2* sv = reinterpret_cast<float2*>(sbuf);
    if (t < 5) counts[t] = 0;
    {
        float s0 = scores[row * NN + t],       s1 = scores[row * NN + t + 256];
        float r0 = relevance[row * NN + t],    r1 = relevance[row * NN + t + 256];
        sv[t]       = make_float2(s0, r0);
        sv[t + 256] = make_float2(s1, r1);
        __syncthreads();
        atomicAdd(&counts[(int)r0], 1);
        atomicAdd(&counts[(int)r1], 1);
    }

    // rank scan: 4 threads/item, j = 4*jj+part (broadcast-uniform LDS.64),
    // tie-break (j < i) via loop split -> no runtime index compares.
    const int   i    = q * 64 + (t >> 2);
    const int   part = t & 3;
    const float2 self = sv[i];
    const float si  = self.x;
    const int   ri  = (int)self.y;
    const int   thr = (i - part + 3) >> 2;     // #jj with 4jj+part < i

    int rk = 0, jj = 0;
    #pragma unroll 8
    for (; jj < thr; ++jj) rk += (sv[4 * jj + part].x >= si);   // j < i
    #pragma unroll 8
    for (; jj < 128; ++jj) rk += (sv[4 * jj + part].x > si);    // j >= i
    rk += __shfl_down_sync(0xffffffffu, rk, 2, 4);
    rk += __shfl_down_sync(0xffffffffu, rk, 1, 4);

    __syncthreads();                           // histogram complete
    const int c4 = counts[4], c3 = counts[3], c2 = counts[2], c1 = counts[1];

    if (part == 0) {
        int base = (ri == 4) ? 0
                 : (ri == 3) ? c4
                 : (ri == 2) ? c4 + c3
                 : (ri == 1) ? c4 + c3 + c2
                             : c4 + c3 + c2 + c1;
        int cr = (ri == 4) ? c4 : (ri == 3) ? c3 : (ri == 2) ? c2
               : (ri == 1) ? c1 : (NN - (c4 + c3 + c2 + c1));
        unsigned slot = atomicAdd(&g_slot[row * 5 + ri], 1u);
        float g = (float)((1 << ri) - 1);
        float d = __fdividef(1.0f, __log2f((float)(rk + 3)));  // rank = rk+1
        g_items[row * NN + base + (int)slot] =
            make_float4(g, d, __expf(si), __int_as_float(base + cr));
    }

    // Row constants (q==0 only; block-uniform branch)
    if (q == 0) {
        int b4 = c4, b3 = b4 + c3, b2 = b3 + c2, b1 = b2 + c1;
        float v = 0.0f;
        #pragma unroll
        for (int h = 0; h < 2; ++h) {
            int p = t + h * 256;
            float gl = p < b4 ? 15.f : p < b3 ? 7.f : p < b2 ? 3.f : p < b1 ? 1.f : 0.f;
            v += __fdividef(gl, __log2f((float)(p + 2)));
        }
        #pragma unroll
        for (int o = 16; o > 0; o >>= 1) v += __shfl_down_sync(0xffffffffu, v, o);
        if ((t & 31) == 0) wred[t >> 5] = v;
        __syncthreads();
        if (t == 0) {
            float idcg = fmaxf(wred[0] + wred[1] + wred[2] + wred[3] +
                               wred[4] + wred[5] + wred[6] + wred[7], EPS);
            int c0 = NN - (c4 + c3 + c2 + c1);
            float sq = (float)c4 * c4 + (float)c3 * c3 + (float)c2 * c2 +
                       (float)c1 * c1 + (float)c0 * c0;
            float cntf = 0.5f * ((float)NN * NN - sq);
            g_rowScale[row] = 0.6931471805599453f /
                              (idcg * (cntf + EPS)) / (float)BB;
        }
    }

    // ---------------- Row barrier ----------------
    __syncthreads();
    if (t == 0) {
        __threadfence();
        atomicAdd(&g_rowDone[row], 1u);
        while (atomicAdd(&g_rowDone[row], 0u) < 8u) {}
    }
    __syncthreads();

    // ---------------- Phase 2: valid pairs ----------------
    float4* sj = sbuf;
    sj[t]       = __ldcg(&g_items[row * NN + t]);
    sj[t + 256] = __ldcg(&g_items[row * NN + t + 256]);
    __syncthreads();

    float acc = 0.0f;
    {   // item A: sorted position t (lo non-decreasing -> warp min at lane 0)
        float4 mi = sj[t];
        int lo  = __float_as_int(mi.w);
        int lou = __shfl_sync(0xffffffffu, lo, 0);
        int len = NN - lou;
        int j0 = lou + ((q * len) >> 3);
        int j1 = lou + (((q + 1) * len) >> 3);
        float gi = mi.x, di = mi.y;
        float Ei = __fdividef(1.0f, mi.z);              // exp(-s_i)
        #pragma unroll 4
        for (int j = j0; j < j1; ++j) {                 // j warp-uniform: broadcast LDS
            float4 mj = sj[j];
            float w = fmaxf(gi - mj.x, 0.0f) * fabsf(di - mj.y);
            float u = Ei * mj.z;                        // exp(s_j - s_i)
            acc = fmaf(w, __log2f(1.0f + u), acc);      // ln2 folded in rowScale
        }
    }
    {   // item B: sorted position 511-t (warp min lo at lane 31)
        float4 mi = sj[NN - 1 - t];
        int lo  = __float_as_int(mi.w);
        int lou = __shfl_sync(0xffffffffu, lo, 31);
        int len = NN - lou;
        int j0 = lou + ((q * len) >> 3);
        int j1 = lou + (((q + 1) * len) >> 3);
        float gi = mi.x, di = mi.y;
        float Ei = __fdividef(1.0f, mi.z);
        #pragma unroll 4
        for (int j = j0; j < j1; ++j) {
            float4 mj = sj[j];
            float w = fmaxf(gi - mj.x, 0.0f) * fabsf(di - mj.y);
            float u = Ei * mj.z;
            acc = fmaf(w, __log2f(1.0f + u), acc);
        }
    }

    // block reduce (8 warps)
    #pragma unroll
    for (int o = 16; o > 0; o >>= 1) acc += __shfl_down_sync(0xffffffffu, acc, o);
    if ((t & 31) == 0) ws[t >> 5] = acc;
    __syncthreads();
    if (t < 32) {
        float bs = (t < 8) ? ws[t] : 0.0f;
        #pragma unroll
        for (int o = 4; o > 0; o >>= 1) bs += __shfl_down_sync(0xffffffffu, bs, o);
        if (t == 0) {
            atomicAdd(&g_accum, bs * __ldcg(&g_rowScale[row]));
            __threadfence();
            unsigned n = atomicAdd(&g_count, 1u);
            if (n == 8u * BB - 1u) {                // last block finalizes + resets
                out[0] = atomicAdd(&g_accum, 0.0f);
                g_accum = 0.0f;
                g_count = 0u;
                for (int k = 0; k < BB; ++k)     g_rowDone[k] = 0u;
                for (int k = 0; k < BB * 5; ++k) g_slot[k] = 0u;
            }
        }
    }
}

extern "C" void kernel_launch(void* const* d_in, const int* in_sizes, int n_in,
                              void* d_out, int out_size) {
    const float* scores    = (const float*)d_in[0];
    const float* relevance = (const float*)d_in[1];
    float* out = (float*)d_out;

    lr_fused<<<dim3(8, BB), 256>>>(scores, relevance, out);
}